// round 12
// baseline (speedup 1.0000x reference)
#include <cuda_runtime.h>

// BKT_RNN: B=8192, T=2048, H=4, X=1.
// R12: 8 lanes/row -> 2048 one-warp blocks (3.46 warps/SMSP), with the
// h-state exchange through SHARED MEMORY instead of shuffles (R8's 2048-warp
// shape died of SHFL throughput ~16cyc/SMSP; LDS/STS is ~4). Per step:
// every lane LDS.128's all 4 taus of its row, computes ONE dot + ONE
// tanh.approx (lanes 0-3: p-units, 4-7: h-units), h-lanes STS their new tau
// into the parity buffer, one __syncwarp fences it. tau-form algebra (R10),
// closed-form BKT latent (R4), fused last-block loss.

#define TT 2048
#define BB 8192
#define NBLK (BB / 4)   // 2048 one-warp blocks, 4 rows per warp

__device__ float    g_part[NBLK];
__device__ unsigned g_done = 0;

__device__ __forceinline__ float lg2f(float v) {
    float r; asm("lg2.approx.f32 %0, %1;" : "=f"(r) : "f"(v)); return r;
}
__device__ __forceinline__ float tanhf_a(float v) {
    float r; asm("tanh.approx.f32 %0, %1;" : "=f"(r) : "f"(v)); return r;
}

__global__ void __launch_bounds__(32) k_bkt(
    const float* __restrict__ x,   const float* __restrict__ y,
    const float* __restrict__ Wxh, const float* __restrict__ Whh,
    const float* __restrict__ bh,  const float* __restrict__ Wy,
    const float* __restrict__ by,  const float* __restrict__ prior,
    float* __restrict__ corrects,  float* __restrict__ latents,
    float* __restrict__ loss)
{
    const unsigned FULL = 0xffffffffu;
    const int lane = threadIdx.x;
    const int i    = lane & 7;                  // role within 8-lane group
    const int j    = i & 3;                     // unit index
    const bool is_h = (i & 4) != 0;             // lanes 4-7: h units
    const int r    = lane >> 3;                 // row slot 0..3 in warp
    const int b    = blockIdx.x * 4 + r;

    // Double-buffered tau state per row: [parity][row][unit].
    __shared__ __align__(16) float tau_sm[2][4][4];

    // tau-form weights (sigmoid(z) = 0.5 + 0.5*tanh(z/2)):
    //   h-lane j: z/2 = 0.5*x*Wxh[j] + sum_m tau_m*(Whh[m][j]/4)
    //                   + (0.5*bh[j] + 0.25*sum_m Whh[m][j])
    //   p-lane j: z/2 = sum_m tau_m*(Wy[m][j]/4)
    //                   + (0.5*by[j] + 0.25*sum_m Wy[m][j])
    const float* Wsrc = is_h ? Whh : Wy;
    float Wc[4]; float sw = 0.f;
    #pragma unroll
    for (int m = 0; m < 4; m++) {
        const float w = __ldg(Wsrc + m * 4 + j);
        Wc[m] = 0.25f * w;
        sw   += w;
    }
    const float bias  = 0.5f * __ldg((is_h ? bh : by) + j) + 0.25f * sw;
    const float xcoef = is_h ? (0.5f * __ldg(Wxh + j)) : 0.f;

    // h = 0  ->  tau = -1. h-lanes initialize buffer 0.
    if (is_h) tau_sm[0][r][j] = -1.f;
    __syncwarp();

    float lat  = __ldg(prior);     // tracked identically on lanes 0,1
    float lsum = 0.f;
    const bool odd     = (i & 1) != 0;
    const bool hi2     = (i & 2) != 0;
    const bool is_corr = ((i & 6) == 2);        // lanes 2,3: loss
    const bool is_out  = (i & 4) == 0;          // lanes 0-3 store

    const float4* xp = (const float4*)(x + (size_t)b * TT);
    const float4* yp = (const float4*)(y + (size_t)b * TT);
    // lanes 0/1 -> latents, lanes 2/3 -> corrects.
    float4* op = (float4*)(((i & 2) ? corrects : latents) + (size_t)b * TT);

    float4 xa = __ldcs(xp + 0), xb = __ldcs(xp + 1);
    float4 ya = __ldcs(yp + 0), yb = __ldcs(yp + 1);

    const int NCHUNK = TT / 8;
    for (int c = 0; c < NCHUNK; ++c) {
        float xv[8] = {xa.x, xa.y, xa.z, xa.w, xb.x, xb.y, xb.z, xb.w};
        float yv[8] = {ya.x, ya.y, ya.z, ya.w, yb.x, yb.y, yb.z, yb.w};

        if (c + 1 < NCHUNK) {   // prefetch next chunk under compute
            xa = __ldcs(xp + 2 * c + 2); xb = __ldcs(xp + 2 * c + 3);
            ya = __ldcs(yp + 2 * c + 2); yb = __ldcs(yp + 2 * c + 3);
        }

        float rb[8];
        float prod = 1.f;

        #pragma unroll
        for (int k = 0; k < 8; k++) {
            const int rd = k & 1;        // chunk size 8 is even -> parity
            const int wr = 1 - rd;       //   pattern continuous across chunks

            // ---- all 4 taus of this row in ONE LDS.128 ----
            const float4 tv =
                *reinterpret_cast<const float4*>(&tau_sm[rd][r][0]);

            // ---- one dot + one tanh per lane (unified) ----
            const float zu = fmaf(tv.y, Wc[1],
                              fmaf(tv.x, Wc[0], fmaf(xv[k], xcoef, bias)));
            const float zv = fmaf(tv.w, Wc[3], tv.z * Wc[2]);
            const float tau = tanhf_a(zu + zv);

            // ---- h-lanes publish new tau ----
            if (is_h) tau_sm[wr][r][j] = tau;

            // ---- latent / correct (p-lanes; tau-form) ----
            // lanes 0,1 (l,f): lat' = base + lat*coef,
            //   base = 0.5+0.5*tau_l, coef = -0.5*(tau_l+tau_f)
            // lanes 2,3 (g,s): correct likewise with old lat.
            const float taupo = __shfl_xor_sync(FULL, tau, 1);
            const float coef  = -0.5f * (tau + taupo);
            const float btau  = odd ? taupo : tau;
            const float base  = fmaf(0.5f, btau, 0.5f);
            const float latc  = __shfl_sync(FULL, lat, 0, 8); // lane r*8's lat
            const float res   = fmaf(hi2 ? latc : lat, coef, base);
            lat = res;                  // meaningful on lanes 0,1
            rb[k] = res;

            // ---- loss (lanes 2,3; y in {0,1} -> one factor) ----
            const float cc = fminf(fmaxf(res, 1e-7f), 1.0f - 1e-7f);
            prod *= (yv[k] != 0.f) ? cc : (1.f - cc);
            if ((k & 3) == 3) {
                lsum += is_corr ? lg2f(prod) : 0.f;
                prod = 1.f;
            }

            // ---- fence STS(k) before LDS(k+1) ----
            __syncwarp();
        }

        // lanes 0-3 store: even lane -> elems 0..3, odd -> 4..7.
        if (is_out) {
            const float4 v = odd ? make_float4(rb[4], rb[5], rb[6], rb[7])
                                 : make_float4(rb[0], rb[1], rb[2], rb[3]);
            __stcs(op + 2 * c + (odd ? 1 : 0), v);
        }
    }

    // Warp reduce (each row counted 2x: lanes 2,3) -> per-block slot.
    #pragma unroll
    for (int o = 16; o > 0; o >>= 1)
        lsum += __shfl_xor_sync(FULL, lsum, o);
    if (lane == 0)
        g_part[blockIdx.x] = lsum;
    __threadfence();

    // Last-block-done loss finalize.
    unsigned ticket = 0;
    if (lane == 0) ticket = atomicAdd(&g_done, 1u);
    ticket = __shfl_sync(FULL, ticket, 0);
    if (ticket == NBLK - 1) {
        double acc = 0.0;
        for (int t = lane; t < NBLK; t += 32)
            acc += (double)g_part[t];
        #pragma unroll
        for (int o = 16; o > 0; o >>= 1)
            acc += __shfl_xor_sync(FULL, acc, o);
        if (lane == 0) {
            loss[0] = (float)(-0.6931471805599453 * acc /
                              (2.0 * (double)BB * (double)TT));
            g_done = 0;   // re-arm for graph replay
        }
    }
}

extern "C" void kernel_launch(void* const* d_in, const int* in_sizes, int n_in,
                              void* d_out, int out_size) {
    const float* x     = (const float*)d_in[0];
    const float* y     = (const float*)d_in[1];
    const float* Wxh   = (const float*)d_in[2];
    const float* Whh   = (const float*)d_in[3];
    const float* bh    = (const float*)d_in[4];
    const float* Wy    = (const float*)d_in[5];
    const float* by    = (const float*)d_in[6];
    const float* prior = (const float*)d_in[7];

    float* corrects = (float*)d_out;
    float* latents  = (float*)d_out + (size_t)BB * TT;
    float* loss     = (float*)d_out + 2 * (size_t)BB * TT;

    k_bkt<<<NBLK, 32>>>(x, y, Wxh, Whh, bh, Wy, by, prior,
                        corrects, latents, loss);
}

// round 13
// speedup vs baseline: 1.0422x; 1.0422x over previous
#include <cuda_runtime.h>

// BKT_RNN: B=8192, T=2048, H=4, X=1.
// R13: R11 frame (4 lanes/row, 8 rows/warp, 1024 one-warp blocks, redundant
// per-lane h computation -> shuffle-free tau cycle, tau-form sigmoids via
// tanh.approx, closed-form BKT latent, fused last-block loss) with the
// f32x2 packing REMOVED from the recurrent cycle: scalar FMA trees feed the
// four tanh directly (no pack/unpack MOVs on the chain).

#define TT 2048
#define BB 8192
#define NBLK (BB / 8)   // 1024 one-warp blocks

__device__ float    g_part[NBLK];
__device__ unsigned g_done = 0;

__device__ __forceinline__ float lg2f(float v) {
    float r; asm("lg2.approx.f32 %0, %1;" : "=f"(r) : "f"(v)); return r;
}
__device__ __forceinline__ float tanhf_a(float v) {
    float r; asm("tanh.approx.f32 %0, %1;" : "=f"(r) : "f"(v)); return r;
}

__global__ void __launch_bounds__(32) k_bkt(
    const float* __restrict__ x,   const float* __restrict__ y,
    const float* __restrict__ Wxh, const float* __restrict__ Whh,
    const float* __restrict__ bh,  const float* __restrict__ Wy,
    const float* __restrict__ by,  const float* __restrict__ prior,
    float* __restrict__ corrects,  float* __restrict__ latents,
    float* __restrict__ loss)
{
    const unsigned FULL = 0xffffffffu;
    const int lane = threadIdx.x;
    const int j = lane & 3;                    // p-unit owned by this lane
    const int b = blockIdx.x * 8 + (lane >> 2);

    // tau-form setup: tau_i = tanh(zh_i/2), h_i = 0.5 + 0.5*tau_i.
    // zh_i/2 = 0.5 x Wxh[i] + sum_m tau_m (Whh[m][i]/4)
    //          + (0.5 bh[i] + 0.25 sum_m Whh[m][i])
    // zp_j/2 = sum_m tau_m (Wy[m][j]/4) + (0.5 by[j] + 0.25 sum_m Wy[m][j])
    float W[4][4];     // Whh[m][i]/4   (full matrix, every lane)
    float bhi[4];      // 0.5 bh[i] + 0.25 sum_m Whh[m][i]
    float xw[4];       // 0.5 Wxh[i]
    #pragma unroll
    for (int i = 0; i < 4; i++) {
        float s = 0.f;
        #pragma unroll
        for (int m = 0; m < 4; m++) {
            const float w = __ldg(Whh + m * 4 + i);
            W[m][i] = 0.25f * w;
            s += w;
        }
        bhi[i] = 0.5f * __ldg(bh + i) + 0.25f * s;
        xw[i]  = 0.5f * __ldg(Wxh + i);
    }
    float Pc[4]; float sWy = 0.f;              // own p column
    #pragma unroll
    for (int m = 0; m < 4; m++) {
        const float w = __ldg(Wy + m * 4 + j);
        Pc[m] = 0.25f * w;
        sWy  += w;
    }
    const float bias_p = 0.5f * __ldg(by + j) + 0.25f * sWy;

    float t0 = -1.f, t1 = -1.f, t2 = -1.f, t3 = -1.f;   // h = 0
    float lat  = __ldg(prior);     // maintained locally on lanes 0,1
    float lsum = 0.f;
    const bool odd = (lane & 1) != 0;
    const bool hi2 = (lane & 2) != 0;          // lanes 2,3 -> correct series

    const float4* xp = (const float4*)(x + (size_t)b * TT);
    const float4* yp = (const float4*)(y + (size_t)b * TT);
    float4* op = (float4*)((hi2 ? corrects : latents) + (size_t)b * TT);

    float4 xa = __ldcs(xp + 0), xb = __ldcs(xp + 1);
    float4 ya = __ldcs(yp + 0), yb = __ldcs(yp + 1);

    const int NCHUNK = TT / 8;
    for (int c = 0; c < NCHUNK; ++c) {
        float xv[8] = {xa.x, xa.y, xa.z, xa.w, xb.x, xb.y, xb.z, xb.w};
        float yv[8] = {ya.x, ya.y, ya.z, ya.w, yb.x, yb.y, yb.z, yb.w};

        if (c + 1 < NCHUNK) {   // prefetch next chunk under compute
            xa = __ldcs(xp + 2 * c + 2); xb = __ldcs(xp + 2 * c + 3);
            ya = __ldcs(yp + 2 * c + 2); yb = __ldcs(yp + 2 * c + 3);
        }

        float rb[8];
        float prod = 1.f;

        #pragma unroll
        for (int k = 0; k < 8; k++) {
            // ---- x preamble (off the recurrent cycle) ----
            const float pre0 = fmaf(xv[k], xw[0], bhi[0]);
            const float pre1 = fmaf(xv[k], xw[1], bhi[1]);
            const float pre2 = fmaf(xv[k], xw[2], bhi[2]);
            const float pre3 = fmaf(xv[k], xw[3], bhi[3]);

            // ---- own p pre-activation (OLD taus) + tanh ----
            const float zp = fmaf(t1, Pc[1], fmaf(t0, Pc[0], bias_p)) +
                             fmaf(t3, Pc[3], t2 * Pc[2]);
            const float taup = tanhf_a(zp);    // p_j = 0.5 + 0.5*taup

            // ---- 4 scalar tree dots + 4 tanh (the recurrent cycle) ----
            const float z0 = fmaf(t1, W[1][0], fmaf(t0, W[0][0], pre0)) +
                             fmaf(t3, W[3][0], t2 * W[2][0]);
            const float z1 = fmaf(t1, W[1][1], fmaf(t0, W[0][1], pre1)) +
                             fmaf(t3, W[3][1], t2 * W[2][1]);
            const float z2 = fmaf(t1, W[1][2], fmaf(t0, W[0][2], pre2)) +
                             fmaf(t3, W[3][2], t2 * W[2][2]);
            const float z3 = fmaf(t1, W[1][3], fmaf(t0, W[0][3], pre3)) +
                             fmaf(t3, W[3][3], t2 * W[2][3]);
            t0 = tanhf_a(z0);
            t1 = tanhf_a(z1);
            t2 = tanhf_a(z2);
            t3 = tanhf_a(z3);

            // ---- latent / correct (tau-form, unified) ----
            // lanes 0,1 (l,f): lat' = base + lat*coef,
            //   base = 0.5+0.5*tau_l, coef = -0.5*(tau_l+tau_f)
            // lanes 2,3 (g,s): correct likewise with old lat (shfl feed).
            const float taupo = __shfl_xor_sync(FULL, taup, 1);
            const float coef  = -0.5f * (taup + taupo);
            const float btau  = odd ? taupo : taup;
            const float base  = fmaf(0.5f, btau, 0.5f);
            const float latc  = __shfl_sync(FULL, lat, 0, 4);
            const float res   = fmaf(hi2 ? latc : lat, coef, base);
            lat = res;                 // meaningful on lanes 0,1
            rb[k] = res;

            // ---- loss (lanes 2,3; y in {0,1} -> one factor) ----
            const float cc = fminf(fmaxf(res, 1e-7f), 1.0f - 1e-7f);
            prod *= (yv[k] != 0.f) ? cc : (1.f - cc);
            if ((k & 3) == 3) {
                lsum += hi2 ? lg2f(prod) : 0.f;
                prod = 1.f;
            }
        }

        const float4 v = odd ? make_float4(rb[4], rb[5], rb[6], rb[7])
                             : make_float4(rb[0], rb[1], rb[2], rb[3]);
        __stcs(op + 2 * c + (odd ? 1 : 0), v);
    }

    // Warp reduce (each row counted 2x: lanes 2,3) -> per-block slot.
    #pragma unroll
    for (int o = 16; o > 0; o >>= 1)
        lsum += __shfl_xor_sync(FULL, lsum, o);
    if (lane == 0)
        g_part[blockIdx.x] = lsum;
    __threadfence();

    // Last-block-done loss finalize.
    unsigned ticket = 0;
    if (lane == 0) ticket = atomicAdd(&g_done, 1u);
    ticket = __shfl_sync(FULL, ticket, 0);
    if (ticket == NBLK - 1) {
        double acc = 0.0;
        for (int i = lane; i < NBLK; i += 32)
            acc += (double)g_part[i];
        #pragma unroll
        for (int o = 16; o > 0; o >>= 1)
            acc += __shfl_xor_sync(FULL, acc, o);
        if (lane == 0) {
            loss[0] = (float)(-0.6931471805599453 * acc /
                              (2.0 * (double)BB * (double)TT));
            g_done = 0;   // re-arm for graph replay
        }
    }
}

extern "C" void kernel_launch(void* const* d_in, const int* in_sizes, int n_in,
                              void* d_out, int out_size) {
    const float* x     = (const float*)d_in[0];
    const float* y     = (const float*)d_in[1];
    const float* Wxh   = (const float*)d_in[2];
    const float* Whh   = (const float*)d_in[3];
    const float* bh    = (const float*)d_in[4];
    const float* Wy    = (const float*)d_in[5];
    const float* by    = (const float*)d_in[6];
    const float* prior = (const float*)d_in[7];

    float* corrects = (float*)d_out;
    float* latents  = (float*)d_out + (size_t)BB * TT;
    float* loss     = (float*)d_out + 2 * (size_t)BB * TT;

    k_bkt<<<NBLK, 32>>>(x, y, Wxh, Whh, bh, Wy, by, prior,
                        corrects, latents, loss);
}